// round 14
// baseline (speedup 1.0000x reference)
#include <cuda_runtime.h>
#include <math.h>
#include <cstdint>

#define TOTAL 4608
#define DMODEL 768
#define DFF 3072

// -------- scratch --------
__device__ uint32_t g_xnb  [TOTAL * 384];
__device__ float    g_qkv  [TOTAL * 2304];
__device__ uint32_t g_attnb[TOTAL * 384];
__device__ float    g_x1   [TOTAL * 768];
__device__ uint32_t g_hb   [TOTAL * 1536];
__device__ uint32_t g_wq   [884736];
__device__ uint32_t g_wp   [294912];
__device__ uint32_t g_w1   [1179648];
__device__ uint32_t g_w2   [1179648];

__constant__ int c_cu[9]     = {0, 1024, 1920, 2688, 3328, 3840, 4288, 4544, 4608};
__constant__ int c_pfx128[9] = {0, 8, 15, 21, 26, 30, 34, 36, 37};

__device__ __forceinline__ uint32_t smem_u32(const void* p) {
    uint32_t a;
    asm("{ .reg .u64 t; cvta.to.shared.u64 t, %1; cvt.u32.u64 %0, t; }" : "=r"(a) : "l"(p));
    return a;
}
__device__ __forceinline__ uint32_t pack_bf16x2(float lo, float hi) {
    uint32_t u;
    asm("cvt.rn.bf16x2.f32 %0, %1, %2;" : "=r"(u) : "f"(hi), "f"(lo));
    return u;
}
__device__ __forceinline__ uint16_t f2bf16(float v) {
    uint16_t h;
    asm("cvt.rn.bf16.f32 %0, %1;" : "=h"(h) : "f"(v));
    return h;
}
__device__ __forceinline__ float fexp2nc(float t) {
    float n = rintf(t);
    float f = t - n;
    float p = 8.98934e-3f;
    p = fmaf(p, f, 5.58263e-2f);
    p = fmaf(p, f, 2.40153e-1f);
    p = fmaf(p, f, 6.93147e-1f);
    p = fmaf(p, f, 1.0f);
    return __int_as_float(__float_as_int(p) + (((int)n) << 23));
}

#define MMA_BF16(d0,d1,d2,d3,a0,a1,a2,a3,b0,b1) \
    asm volatile("mma.sync.aligned.m16n8k16.row.col.f32.bf16.bf16.f32 " \
        "{%0,%1,%2,%3}, {%4,%5,%6,%7}, {%8,%9}, {%0,%1,%2,%3};" \
        : "+f"(d0), "+f"(d1), "+f"(d2), "+f"(d3) \
        : "r"(a0), "r"(a1), "r"(a2), "r"(a3), "r"(b0), "r"(b1))

#define LDSM4(r0,r1,r2,r3,addr) \
    asm volatile("ldmatrix.sync.aligned.m8n8.x4.shared.b16 {%0,%1,%2,%3}, [%4];" \
        : "=r"(r0), "=r"(r1), "=r"(r2), "=r"(r3) : "r"(addr))

#define CP16(dst, src) \
    asm volatile("cp.async.cg.shared.global [%0], [%1], 16;" :: "r"(dst), "l"(src))
#define CP_COMMIT() asm volatile("cp.async.commit_group;" ::: "memory")
#define CP_WAIT1()  asm volatile("cp.async.wait_group 1;" ::: "memory")
#define CP_WAIT0()  asm volatile("cp.async.wait_group 0;" ::: "memory")

// ---------------- f32 -> bf16x2 convert ----------------
__global__ __launch_bounds__(256) void cvt_bf16(const float* __restrict__ src,
                                                uint32_t* __restrict__ dst, int n4) {
    int i = blockIdx.x * 256 + threadIdx.x;
    if (i < n4) {
        float4 v = ((const float4*)src)[i];
        ((uint2*)dst)[i] = make_uint2(pack_bf16x2(v.x, v.y), pack_bf16x2(v.z, v.w));
    }
}

// ---------------- LayerNorm: warp per row, bf16 output ----------------
__global__ __launch_bounds__(256) void ln_kernel(const float* __restrict__ x,
                                                 const float* __restrict__ w,
                                                 const float* __restrict__ b,
                                                 uint32_t* __restrict__ out) {
    int row  = blockIdx.x * 8 + (threadIdx.x >> 5);
    int lane = threadIdx.x & 31;
    const float* xr = x + (size_t)row * DMODEL;
    float4 v[6];
    float s = 0.f, ss = 0.f;
#pragma unroll
    for (int i = 0; i < 6; i++) {
        v[i] = *(const float4*)(xr + lane * 4 + i * 128);
        s  += v[i].x + v[i].y + v[i].z + v[i].w;
        ss += v[i].x * v[i].x + v[i].y * v[i].y + v[i].z * v[i].z + v[i].w * v[i].w;
    }
#pragma unroll
    for (int off = 16; off; off >>= 1) {
        s  += __shfl_xor_sync(0xffffffffu, s, off);
        ss += __shfl_xor_sync(0xffffffffu, ss, off);
    }
    float mu  = s * (1.f / DMODEL);
    float var = ss * (1.f / DMODEL) - mu * mu;
    float rstd = rsqrtf(var + 1e-6f);
    uint32_t* orow = out + (size_t)row * 384;
#pragma unroll
    for (int i = 0; i < 6; i++) {
        int c = lane * 4 + i * 128;
        float4 wv = *(const float4*)(w + c);
        float4 bv = *(const float4*)(b + c);
        float o0 = (v[i].x - mu) * rstd * wv.x + bv.x;
        float o1 = (v[i].y - mu) * rstd * wv.y + bv.y;
        float o2 = (v[i].z - mu) * rstd * wv.z + bv.z;
        float o3 = (v[i].w - mu) * rstd * wv.w + bv.w;
        *(uint2*)(orow + lane * 2 + i * 64) =
            make_uint2(pack_bf16x2(o0, o1), pack_bf16x2(o2, o3));
    }
}

// ---------------- BF16 GEMM: cp.async 3-stage + ldmatrix fragments ----------------
#define SKB 36
#define STG_U (128 * SKB)
#define STAGE_U (2 * STG_U)
#define G_SMEM_BYTES (3 * STAGE_U * 4)

template <int EPI>
__global__ __launch_bounds__(256, 2)
void gemm_bf16(const uint32_t* __restrict__ A, const uint32_t* __restrict__ B,
               const float* __restrict__ bias, void* __restrict__ Cout,
               int K, int N, const float* __restrict__ res, const float* __restrict__ gamma) {
    extern __shared__ uint32_t gsm[];
    uint32_t sbase = smem_u32(gsm);

    int tid = threadIdx.x, wid = tid >> 5, lane = tid & 31;
    int g = lane >> 2, t4 = lane & 3;
    int mw = (wid & 1) * 64;
    int nw = (wid >> 1) * 32;
    int bm = blockIdx.x * 128, bn = blockIdx.y * 128;

    int lrow  = lane & 15;          // ldmatrix row within 16-row group
    int khalf = lane >> 4;          // 0: k cols 0-7, 1: k cols 8-15

    float acc[4][4][4];
#pragma unroll
    for (int i = 0; i < 4; i++)
#pragma unroll
        for (int j = 0; j < 4; j++)
#pragma unroll
            for (int q = 0; q < 4; q++) acc[i][j][q] = 0.f;

    int K2 = K >> 1;
    const uint32_t* Ap[4];
    const uint32_t* Bp[4];
    uint32_t sdA[4];
#pragma unroll
    for (int j = 0; j < 4; j++) {
        int fi = tid + 256 * j;
        int row = fi >> 3, ch = fi & 7;
        Ap[j] = A + (size_t)(bm + row) * K2 + ch * 4;
        Bp[j] = B + (size_t)(bn + row) * K2 + ch * 4;
        sdA[j] = (row * SKB + ch * 4) * 4;
    }

    // ldmatrix row byte offsets (within a stage)
    uint32_t arow[4], brow[2];
#pragma unroll
    for (int mt = 0; mt < 4; mt++) arow[mt] = (uint32_t)(mw + mt * 16 + lrow) * (SKB * 4);
#pragma unroll
    for (int np = 0; np < 2; np++) brow[np] = (uint32_t)(nw + np * 16 + lrow) * (SKB * 4) + STG_U * 4;

    int NC = K >> 6;
#pragma unroll
    for (int st = 0; st < 2; st++) {
#pragma unroll
        for (int j = 0; j < 4; j++) {
            CP16(sbase + st * (STAGE_U * 4) + sdA[j], Ap[j] + st * 32);
            CP16(sbase + st * (STAGE_U * 4) + STG_U * 4 + sdA[j], Bp[j] + st * 32);
        }
        CP_COMMIT();
    }

    for (int c = 0; c < NC; c++) {
        if (c < NC - 1) CP_WAIT1(); else CP_WAIT0();
        __syncthreads();
        if (c + 2 < NC) {
            int st = (c + 2) % 3;
#pragma unroll
            for (int j = 0; j < 4; j++) {
                CP16(sbase + st * (STAGE_U * 4) + sdA[j], Ap[j] + (c + 2) * 32);
                CP16(sbase + st * (STAGE_U * 4) + STG_U * 4 + sdA[j], Bp[j] + (c + 2) * 32);
            }
            CP_COMMIT();
        }
        uint32_t stg = sbase + (c % 3) * (STAGE_U * 4);
#pragma unroll
        for (int s = 0; s < 4; s++) {
            uint32_t koff = (s * 8 + khalf * 4) * 4;
            uint32_t af[4][4], bf[4][2];
            LDSM4(bf[0][0], bf[1][0], bf[0][1], bf[1][1], stg + brow[0] + koff);
            LDSM4(bf[2][0], bf[3][0], bf[2][1], bf[3][1], stg + brow[1] + koff);
#pragma unroll
            for (int mt = 0; mt < 4; mt++)
                LDSM4(af[mt][0], af[mt][1], af[mt][2], af[mt][3], stg + arow[mt] + koff);
#pragma unroll
            for (int mt = 0; mt < 4; mt++)
#pragma unroll
                for (int nt = 0; nt < 4; nt++)
                    MMA_BF16(acc[mt][nt][0], acc[mt][nt][1], acc[mt][nt][2], acc[mt][nt][3],
                             af[mt][0], af[mt][1], af[mt][2], af[mt][3], bf[nt][0], bf[nt][1]);
        }
    }

#pragma unroll
    for (int mt = 0; mt < 4; mt++) {
#pragma unroll
        for (int half = 0; half < 2; half++) {
            int r = bm + mw + mt * 16 + g + half * 8;
            const float* resr = (EPI == 2) ? res + (size_t)r * N : nullptr;
#pragma unroll
            for (int nt = 0; nt < 4; nt++) {
                int cn = bn + nw + nt * 8 + 2 * t4;
                float v0 = acc[mt][nt][half * 2 + 0] + bias[cn];
                float v1 = acc[mt][nt][half * 2 + 1] + bias[cn + 1];
                if (EPI == 1) {
                    v0 = 0.5f * v0 * (1.f + erff(v0 * 0.70710678118654752f));
                    v1 = 0.5f * v1 * (1.f + erff(v1 * 0.70710678118654752f));
                    ((uint32_t*)Cout)[(size_t)r * (N >> 1) + (cn >> 1)] = pack_bf16x2(v0, v1);
                } else if (EPI == 2) {
                    v0 = resr[cn] + gamma[cn] * v0;
                    v1 = resr[cn + 1] + gamma[cn + 1] * v1;
                    *(float2*)((float*)Cout + (size_t)r * N + cn) = make_float2(v0, v1);
                } else {
                    *(float2*)((float*)Cout + (size_t)r * N + cn) = make_float2(v0, v1);
                }
            }
        }
    }
}

// ---------------- Flash attention v5: bf16 + ldmatrix K/V fragments ----------------
#define KST 36
#define VOFF (64 * KST)
#define ABUF (VOFF + 64 * KST + 32)
__device__ __forceinline__ int vrow(int d) { return d * KST + ((d >> 4) << 3); }

__global__ __launch_bounds__(256) void attn_mma2(const float* __restrict__ qkv,
                                                 uint32_t* __restrict__ outb) {
    __shared__ uint32_t sm[2 * ABUF];
    uint32_t sb = smem_u32(sm);

    int bx = blockIdx.x, h = blockIdx.y;
    int s = 0;
#pragma unroll
    for (int i = 1; i < 8; i++) s += (bx >= c_pfx128[i]) ? 1 : 0;
    int q0   = (bx - c_pfx128[s]) * 128;
    int base = c_cu[s];
    int L    = c_cu[s + 1] - base;

    int tid = threadIdx.x, wid = tid >> 5, lane = tid & 31;
    int g = lane >> 2, t4 = lane & 3;
    int ltok = tid >> 2;
    int dg   = (tid & 3) << 4;
    int lrow  = lane & 15;
    int khalf = lane >> 4;

    // ---- preload Q fragments (bf16, scaled by log2e/8) ----
    const float QSC = 0.18033688011112042f;
    uint32_t qa[4][4];
    {
        int r0 = q0 + wid * 16 + g, r1 = r0 + 8;
        bool v0 = r0 < L, v1 = r1 < L;
        const float* p0 = qkv + (size_t)(base + (v0 ? r0 : 0)) * 2304 + h * 64;
        const float* p1 = qkv + (size_t)(base + (v1 ? r1 : 0)) * 2304 + h * 64;
#pragma unroll
        for (int st = 0; st < 4; st++) {
            int k0 = 16 * st + 2 * t4, k1 = k0 + 8;
            qa[st][0] = v0 ? pack_bf16x2(p0[k0] * QSC, p0[k0 + 1] * QSC) : 0u;
            qa[st][1] = v1 ? pack_bf16x2(p1[k0] * QSC, p1[k0 + 1] * QSC) : 0u;
            qa[st][2] = v0 ? pack_bf16x2(p0[k1] * QSC, p0[k1 + 1] * QSC) : 0u;
            qa[st][3] = v1 ? pack_bf16x2(p1[k1] * QSC, p1[k1 + 1] * QSC) : 0u;
        }
    }

    // ldmatrix row byte offsets: K rows (token), V rows (d)
    uint32_t krow4[4], vrow4[4];
#pragma unroll
    for (int np = 0; np < 4; np++) {
        krow4[np] = (uint32_t)(np * 16 + lrow) * (KST * 4);
        vrow4[np] = (uint32_t)(vrow(np * 16 + lrow)) * 4 + VOFF * 4;
    }

    float l0 = 0.f, l1 = 0.f;
    float acco[8][4];
#pragma unroll
    for (int nt = 0; nt < 8; nt++)
#pragma unroll
        for (int q = 0; q < 4; q++) acco[nt][q] = 0.f;

    int nkt = (L + 63) >> 6;

    float4 kr[4], vr[4];
    bool kvalid;
    {
        int r = ltok;
        kvalid = r < L;
        const float* kp = qkv + (size_t)(base + (kvalid ? r : 0)) * 2304 + 768 + h * 64 + dg;
#pragma unroll
        for (int j = 0; j < 4; j++) {
            kr[j] = kvalid ? *(const float4*)(kp + j * 4) : make_float4(0, 0, 0, 0);
            vr[j] = kvalid ? *(const float4*)(kp + 768 + j * 4) : make_float4(0, 0, 0, 0);
        }
    }
    {
        uint32_t* Kb = sm;
        uint32_t kb2 = ltok * KST + (dg >> 1);
        *(uint4*)&Kb[kb2] = make_uint4(pack_bf16x2(kr[0].x, kr[0].y), pack_bf16x2(kr[0].z, kr[0].w),
                                       pack_bf16x2(kr[1].x, kr[1].y), pack_bf16x2(kr[1].z, kr[1].w));
        *(uint4*)&Kb[kb2 + 4] = make_uint4(pack_bf16x2(kr[2].x, kr[2].y), pack_bf16x2(kr[2].z, kr[2].w),
                                           pack_bf16x2(kr[3].x, kr[3].y), pack_bf16x2(kr[3].z, kr[3].w));
        uint16_t* Vh = (uint16_t*)(Kb + VOFF);
#pragma unroll
        for (int j = 0; j < 4; j++)
#pragma unroll
            for (int c = 0; c < 4; c++)
                Vh[vrow(dg + 4 * j + c) * 2 + ltok] = f2bf16((&vr[j].x)[c]);
    }

    for (int kt = 0; kt < nkt; kt++) {
        int kb = kt << 6;
        if (kt + 1 < nkt) {
            int r = kb + 64 + ltok;
            kvalid = r < L;
            const float* kp = qkv + (size_t)(base + (kvalid ? r : 0)) * 2304 + 768 + h * 64 + dg;
#pragma unroll
            for (int j = 0; j < 4; j++) {
                kr[j] = kvalid ? *(const float4*)(kp + j * 4) : make_float4(0, 0, 0, 0);
                vr[j] = kvalid ? *(const float4*)(kp + 768 + j * 4) : make_float4(0, 0, 0, 0);
            }
        }
        __syncthreads();

        uint32_t tb = sb + (kt & 1) * (ABUF * 4);

        // ---- S = Q K^T ----
        float sc[8][4];
#pragma unroll
        for (int nt = 0; nt < 8; nt++) {
            sc[nt][0] = 0.f; sc[nt][1] = 0.f; sc[nt][2] = 0.f; sc[nt][3] = 0.f;
        }
#pragma unroll
        for (int st = 0; st < 4; st++) {
            uint32_t koff = (st * 8 + khalf * 4) * 4;
            uint32_t kf[8][2];
#pragma unroll
            for (int np = 0; np < 4; np++)
                LDSM4(kf[2 * np][0], kf[2 * np + 1][0], kf[2 * np][1], kf[2 * np + 1][1],
                      tb + krow4[np] + koff);
#pragma unroll
            for (int nt = 0; nt < 8; nt++)
                MMA_BF16(sc[nt][0], sc[nt][1], sc[nt][2], sc[nt][3],
                         qa[st][0], qa[st][1], qa[st][2], qa[st][3], kf[nt][0], kf[nt][1]);
        }

        // ---- STS next tile ----
        if (kt + 1 < nkt) {
            uint32_t* Kn = sm + ((kt + 1) & 1) * ABUF;
            uint32_t kb2 = ltok * KST + (dg >> 1);
            *(uint4*)&Kn[kb2] = make_uint4(pack_bf16x2(kr[0].x, kr[0].y), pack_bf16x2(kr[0].z, kr[0].w),
                                           pack_bf16x2(kr[1].x, kr[1].y), pack_bf16x2(kr[1].z, kr[1].w));
            *(uint4*)&Kn[kb2 + 4] = make_uint4(pack_bf16x2(kr[2].x, kr[2].y), pack_bf16x2(kr[2].z, kr[2].w),
                                               pack_bf16x2(kr[3].x, kr[3].y), pack_bf16x2(kr[3].z, kr[3].w));
            uint16_t* Vh = (uint16_t*)(Kn + VOFF);
#pragma unroll
            for (int j = 0; j < 4; j++)
#pragma unroll
                for (int c = 0; c < 4; c++)
                    Vh[vrow(dg + 4 * j + c) * 2 + ltok] = f2bf16((&vr[j].x)[c]);
        }

        // ---- mask + fixed-max softmax (exp2 domain) ----
        if (kb + 64 > L) {
#pragma unroll
            for (int nt = 0; nt < 8; nt++) {
                int col = kb + nt * 8 + 2 * t4;
                if (col >= L)     { sc[nt][0] = -126.f; sc[nt][2] = -126.f; }
                if (col + 1 >= L) { sc[nt][1] = -126.f; sc[nt][3] = -126.f; }
            }
        }
#pragma unroll
        for (int nt = 0; nt < 8; nt++) {
            float p0 = fexp2nc(sc[nt][0]);
            float p1 = fexp2nc(sc[nt][1]);
            float p2 = fexp2nc(sc[nt][2]);
            float p3 = fexp2nc(sc[nt][3]);
            l0 += p0 + p1; l1 += p2 + p3;
            sc[nt][0] = p0; sc[nt][1] = p1; sc[nt][2] = p2; sc[nt][3] = p3;
        }

        // ---- O += P V ----
#pragma unroll
        for (int st = 0; st < 4; st++) {
            uint32_t pa0 = pack_bf16x2(sc[2 * st][0], sc[2 * st][1]);
            uint32_t pa1 = pack_bf16x2(sc[2 * st][2], sc[2 * st][3]);
            uint32_t pa2 = pack_bf16x2(sc[2 * st + 1][0], sc[2 * st + 1][1]);
            uint32_t pa3 = pack_bf16x2(sc[2 * st + 1][2], sc[2 * st + 1][3]);
            uint32_t koff = (st * 8 + khalf * 4) * 4;
            uint32_t vf[8][2];
#pragma unroll
            for (int np = 0; np < 4; np++)
                LDSM4(vf[2 * np][0], vf[2 * np + 1][0], vf[2 * np][1], vf[2 * np + 1][1],
                      tb + vrow4[np] + koff);
#pragma unroll
            for (int nt = 0; nt < 8; nt++)
                MMA_BF16(acco[nt][0], acco[nt][1], acco[nt][2], acco[nt][3],
                         pa0, pa1, pa2, pa3, vf[nt][0], vf[nt][1]);
        }
    }

    // ---- final row-sum reduction + write O (bf16) ----
#pragma unroll
    for (int off = 1; off <= 2; off <<= 1) {
        l0 += __shfl_xor_sync(0xffffffffu, l0, off);
        l1 += __shfl_xor_sync(0xffffffffu, l1, off);
    }
    float inv0 = 1.f / l0, inv1 = 1.f / l1;
    int r0 = q0 + wid * 16 + g, r1 = r0 + 8;
#pragma unroll
    for (int nt = 0; nt < 8; nt++) {
        int col = h * 64 + nt * 8 + 2 * t4;
        if (r0 < L)
            outb[(size_t)(base + r0) * 384 + (col >> 1)] =
                pack_bf16x2(acco[nt][0] * inv0, acco[nt][1] * inv0);
        if (r1 < L)
            outb[(size_t)(base + r1) * 384 + (col >> 1)] =
                pack_bf16x2(acco[nt][2] * inv1, acco[nt][3] * inv1);
    }
}

// ---------------- launch ----------------
extern "C" void kernel_launch(void* const* d_in, const int* in_sizes, int n_in,
                              void* d_out, int out_size) {
    const float* x      = (const float*)d_in[0];
    const float* n1w    = (const float*)d_in[1];
    const float* n1b    = (const float*)d_in[2];
    const float* qkv_w  = (const float*)d_in[3];
    const float* qkv_b  = (const float*)d_in[4];
    const float* proj_w = (const float*)d_in[5];
    const float* proj_b = (const float*)d_in[6];
    const float* ls1    = (const float*)d_in[7];
    const float* n2w    = (const float*)d_in[8];
    const float* n2b    = (const float*)d_in[9];
    const float* fc1_w  = (const float*)d_in[10];
    const float* fc1_b  = (const float*)d_in[11];
    const float* fc2_w  = (const float*)d_in[12];
    const float* fc2_b  = (const float*)d_in[13];
    const float* ls2    = (const float*)d_in[14];
    float* out = (float*)d_out;

    uint32_t *xnb, *attnb, *hb, *wq, *wp, *w1, *w2;
    float *qkvf, *x1;
    cudaGetSymbolAddress((void**)&xnb,   g_xnb);
    cudaGetSymbolAddress((void**)&qkvf,  g_qkv);
    cudaGetSymbolAddress((void**)&attnb, g_attnb);
    cudaGetSymbolAddress((void**)&x1,    g_x1);
    cudaGetSymbolAddress((void**)&hb,    g_hb);
    cudaGetSymbolAddress((void**)&wq,    g_wq);
    cudaGetSymbolAddress((void**)&wp,    g_wp);
    cudaGetSymbolAddress((void**)&w1,    g_w1);
    cudaGetSymbolAddress((void**)&w2,    g_w2);

    cudaFuncSetAttribute(gemm_bf16<0>, cudaFuncAttributeMaxDynamicSharedMemorySize, G_SMEM_BYTES);
    cudaFuncSetAttribute(gemm_bf16<1>, cudaFuncAttributeMaxDynamicSharedMemorySize, G_SMEM_BYTES);
    cudaFuncSetAttribute(gemm_bf16<2>, cudaFuncAttributeMaxDynamicSharedMemorySize, G_SMEM_BYTES);

    cvt_bf16<<<1728, 256>>>(qkv_w, wq, 442368);
    cvt_bf16<<<576, 256>>>(proj_w, wp, 147456);
    ln_kernel<<<576, 256>>>(x, n1w, n1b, xnb);
    gemm_bf16<0><<<dim3(36, 18), 256, G_SMEM_BYTES>>>(xnb, wq, qkv_b, qkvf, 768, 2304, nullptr, nullptr);
    attn_mma2<<<dim3(37, 12), 256>>>(qkvf, attnb);
    gemm_bf16<2><<<dim3(36, 6), 256, G_SMEM_BYTES>>>(attnb, wp, proj_b, x1, 768, 768, x, ls1);
    cvt_bf16<<<2304, 256>>>(fc1_w, w1, 589824);
    cvt_bf16<<<2304, 256>>>(fc2_w, w2, 589824);
    ln_kernel<<<576, 256>>>(x1, n2w, n2b, xnb);
    gemm_bf16<1><<<dim3(36, 24), 256, G_SMEM_BYTES>>>(xnb, w1, fc1_b, hb, 768, 3072, nullptr, nullptr);
    gemm_bf16<2><<<dim3(36, 6), 256, G_SMEM_BYTES>>>(hb, w2, fc2_b, out, 3072, 768, x1, ls2);
}